// round 16
// baseline (speedup 1.0000x reference)
#include <cuda_runtime.h>
#include <cuda_fp16.h>

#define B_  4
#define N_  16384
#define M_  4096
#define K_  16
#define R2  0.25f
#define PRE2 0.33f         // prefilter threshold = R2 + margin (margin >= 3x fp16 err bound)
#define NQ  (B_ * M_)
#define NPAIR (N_ / 2)     // 8192 pair slots per batch
#define LONG_THRESH 4.0f   // |q|^2 above this => long scan, schedule first

// Scratch (device globals; no allocation allowed)
__device__ float4       g_pts[B_ * N_];   // (x, y, z, |p|^2)
__device__ float4       g_n2p[B_ * N_];   // (-2x, -2y, -2z, |p|^2) exact-test array
__device__ uint4        g_hp [B_ * NPAIR];// pair-packed half coords {x2,y2,z2,pad}
__device__ unsigned int g_qctr, g_front, g_back;
__device__ int          g_order[NQ];

// prep: one thread per pair slot (points i = c*64+l and j = i+32).
__global__ __launch_bounds__(256) void prep_kernel(const float* __restrict__ xyz) {
    int t = blockIdx.x * blockDim.x + threadIdx.x;   // 0 .. B_*NPAIR-1
    if (t == 0) { g_qctr = 0; g_front = 0; g_back = 0; }   // graph-replay safe
    if (t >= B_ * NPAIR) return;
    int b  = t >> 13;              // / NPAIR
    int s  = t & (NPAIR - 1);
    int c  = s >> 5;               // 64-point chunk
    int l  = s & 31;
    int gi = b * N_ + c * 64 + l;
    int gj = gi + 32;

    float xi = xyz[3 * gi + 0], yi = xyz[3 * gi + 1], zi = xyz[3 * gi + 2];
    float xj = xyz[3 * gj + 0], yj = xyz[3 * gj + 1], zj = xyz[3 * gj + 2];
    // match jnp.sum(x**2,-1): (x*x + y*y) + z*z, no fma contraction
    float wi = __fadd_rn(__fadd_rn(__fmul_rn(xi, xi), __fmul_rn(yi, yi)), __fmul_rn(zi, zi));
    float wj = __fadd_rn(__fadd_rn(__fmul_rn(xj, xj), __fmul_rn(yj, yj)), __fmul_rn(zj, zj));

    g_pts[gi] = make_float4(xi, yi, zi, wi);
    g_pts[gj] = make_float4(xj, yj, zj, wj);
    // -2*coord is exact (power-of-2 scale + sign flip): exact-test form
    // rn(rn(qw+pw) + dotn) is bit-identical to rn(rn(qw+pw) - rn(2*dot)).
    g_n2p[gi] = make_float4(-2.0f * xi, -2.0f * yi, -2.0f * zi, wi);
    g_n2p[gj] = make_float4(-2.0f * xj, -2.0f * yj, -2.0f * zj, wj);

    __half2 hx = __halves2half2(__float2half_rn(xi), __float2half_rn(xj));
    __half2 hy = __halves2half2(__float2half_rn(yi), __float2half_rn(yj));
    __half2 hz = __halves2half2(__float2half_rn(zi), __float2half_rn(zj));
    uint4 hv;
    hv.x = *(unsigned*)&hx;
    hv.y = *(unsigned*)&hy;
    hv.z = *(unsigned*)&hz;
    hv.w = 0;
    g_hp[t] = hv;
}

// LPT scheduling: long-scan queries (large |q|^2) go to the front of the
// queue, short ones to the back. Processing order doesn't affect results.
__global__ __launch_bounds__(256) void order_kernel(const int* __restrict__ fps_idx) {
    int qid = blockIdx.x * blockDim.x + threadIdx.x;
    if (qid >= NQ) return;
    int b = qid >> 12;
    float w = g_pts[(size_t)b * N_ + fps_idx[qid]].w;
    int pos;
    if (w > LONG_THRESH) pos = (int)atomicAdd(&g_front, 1u);
    else                 pos = NQ - 1 - (int)atomicAdd(&g_back, 1u);
    g_order[pos] = qid;
}

// exact d2 (pre-scaled point): bit-identical to the reference chain.
__device__ __forceinline__ float d2n(float4 q, float4 n) {
    float dotn = __fadd_rn(__fadd_rn(__fmul_rn(q.x, n.x), __fmul_rn(q.y, n.y)),
                           __fmul_rn(q.z, n.z));
    return __fadd_rn(__fadd_rn(q.w, n.w), dotn);
}

// half2 direct-form distance^2 for a point pair (conservative prefilter only)
__device__ __forceinline__ __half2 ddpair(__half2 qx, __half2 qy, __half2 qz, uint4 h) {
    __half2 px = *(__half2*)&h.x;
    __half2 py = *(__half2*)&h.y;
    __half2 pz = *(__half2*)&h.z;
    __half2 dx = __hsub2(qx, px);
    __half2 dy = __hsub2(qy, py);
    __half2 dz = __hsub2(qz, pz);
    __half2 dd = __hmul2(dx, dx);
    dd = __hfma2(dy, dy, dd);
    dd = __hfma2(dz, dz, dd);
    return dd;
}

__global__ __launch_bounds__(256, 4) void sa_kernel(
    const float* __restrict__ feat,
    const int*   __restrict__ fps_idx,
    const float* __restrict__ W1,
    const float* __restrict__ b1,
    const float* __restrict__ W2,
    const float* __restrict__ b2,
    float*       __restrict__ out)
{
    const unsigned FULL = 0xffffffffu;
    int lane = threadIdx.x & 31;

    float w1r[6], w2r[32];
    #pragma unroll
    for (int i = 0; i < 6; i++)  w1r[i] = W1[i * 32 + lane];
    #pragma unroll
    for (int i = 0; i < 32; i++) w2r[i] = W2[i * 32 + lane];
    float b1r = b1[lane];
    float b2r = b2[lane];

    // persistent warp: steal one query at a time, longest-first order
    for (;;) {
        int idx;
        if (lane == 0) idx = (int)atomicAdd(&g_qctr, 1u);
        idx = __shfl_sync(FULL, idx, 0);
        if (idx >= NQ) break;
        int qid = g_order[idx];

        int b = qid >> 12;            // / M_ (4096)
        const float4* __restrict__ pts  = g_pts + (size_t)b * N_;
        const float4* __restrict__ n2pb = g_n2p + (size_t)b * N_;
        const uint4*  __restrict__ hp   = g_hp  + (size_t)b * NPAIR + lane;

        float4 q = pts[fps_idx[qid]];
        __half2 qx2 = __half2half2(__float2half_rn(q.x));
        __half2 qy2 = __half2half2(__float2half_rn(q.y));
        __half2 qz2 = __half2half2(__float2half_rn(q.z));

        // ---- ball query: first K_ in-ball indices in ascending order ----
        // fp16 pair prefilter (2 points/lane), exact recheck on candidates.
        int found  = 0;
        int my_idx = 0;               // lane k (k<K_) owns neighbor k
        for (int base = 0; base < N_; base += 256, hp += 128) {
            uint4 h0 = hp[0];
            uint4 h1 = hp[32];
            uint4 h2 = hp[64];
            uint4 h3 = hp[96];
            __half2 d0 = ddpair(qx2, qy2, qz2, h0);
            __half2 d1 = ddpair(qx2, qy2, qz2, h1);
            __half2 d2 = ddpair(qx2, qy2, qz2, h2);
            __half2 d3 = ddpair(qx2, qy2, qz2, h3);
            // lo half of pair = points [base+g*64, +32), hi = [base+g*64+32, +64)
            unsigned c0 = __ballot_sync(FULL, __low2float(d0)  <= PRE2);
            unsigned c1 = __ballot_sync(FULL, __high2float(d0) <= PRE2);
            unsigned c2 = __ballot_sync(FULL, __low2float(d1)  <= PRE2);
            unsigned c3 = __ballot_sync(FULL, __high2float(d1) <= PRE2);
            unsigned c4 = __ballot_sync(FULL, __low2float(d2)  <= PRE2);
            unsigned c5 = __ballot_sync(FULL, __high2float(d2) <= PRE2);
            unsigned c6 = __ballot_sync(FULL, __low2float(d3)  <= PRE2);
            unsigned c7 = __ballot_sync(FULL, __high2float(d3) <= PRE2);
            unsigned any = (c0 | c1) | (c2 | c3) | ((c4 | c5) | (c6 | c7));
            if (any) {
                // exact recheck: candidates only, reference-exact arithmetic
                unsigned cm[8] = {c0, c1, c2, c3, c4, c5, c6, c7};
                unsigned m[8];
                #pragma unroll
                for (int j = 0; j < 8; j++) {
                    bool e = false;
                    if ((cm[j] >> lane) & 1u) {
                        e = d2n(q, n2pb[base + j * 32 + lane]) <= R2;
                    }
                    m[j] = __ballot_sync(FULL, e);
                }
                // parallel rank-select (ascending group/bit == serial walk)
                int s0 = __popc(m[0]);
                int s1 = s0 + __popc(m[1]);
                int s2 = s1 + __popc(m[2]);
                int s3 = s2 + __popc(m[3]);
                int s4 = s3 + __popc(m[4]);
                int s5 = s4 + __popc(m[5]);
                int s6 = s5 + __popc(m[6]);
                int T  = s6 + __popc(m[7]);
                int r  = lane - found;
                if (r >= 0 && r < T && lane < K_) {
                    unsigned mm; int e, off;
                    if (r < s3) {
                        if (r < s1) {
                            if (r < s0) { mm = m[0]; e = 0;  off = 0;  }
                            else        { mm = m[1]; e = s0; off = 32; }
                        } else {
                            if (r < s2) { mm = m[2]; e = s1; off = 64; }
                            else        { mm = m[3]; e = s2; off = 96; }
                        }
                    } else {
                        if (r < s5) {
                            if (r < s4) { mm = m[4]; e = s3; off = 128; }
                            else        { mm = m[5]; e = s4; off = 160; }
                        } else {
                            if (r < s6) { mm = m[6]; e = s5; off = 192; }
                            else        { mm = m[7]; e = s6; off = 224; }
                        }
                    }
                    my_idx = base + off + __fns(mm, 0, (r - e) + 1);
                }
                found += T;
                if (found >= K_) { found = K_; break; }
            }
        }
        // pad missing neighbors with the first valid one (reference
        // semantics); found >= 1 always (query is in its own ball).
        int idx0 = __shfl_sync(FULL, my_idx, 0);
        if (lane >= found) my_idx = idx0;
        int kmax = found;                     // padded dups can't change max

        // ---- MLP + maxpool: lane j owns output channel j ----
        const float* __restrict__ featb = feat + (size_t)b * N_ * 3;
        float acc = -3.402823466e38f;

        #pragma unroll 1
        for (int k = 0; k < kmax; k++) {
            int g = __shfl_sync(FULL, my_idx, k);
            float4 p = pts[g];                    // broadcast load (L1/L2 hit)
            float f0 = featb[3 * g + 0];
            float f1 = featb[3 * g + 1];
            float f2 = featb[3 * g + 2];
            float i0 = p.x - q.x, i1 = p.y - q.y, i2 = p.z - q.z;

            float h1 = b1r;
            h1 += i0 * w1r[0];
            h1 += i1 * w1r[1];
            h1 += i2 * w1r[2];
            h1 += f0 * w1r[3];
            h1 += f1 * w1r[4];
            h1 += f2 * w1r[5];
            h1 = fmaxf(h1, 0.1f * h1);            // leaky relu

            // 4 accumulator chains to break the serial FMA dependency
            float a0 = b2r, a1 = 0.f, a2 = 0.f, a3 = 0.f;
            #pragma unroll
            for (int i = 0; i < 32; i += 4) {
                a0 = fmaf(__shfl_sync(FULL, h1, i + 0), w2r[i + 0], a0);
                a1 = fmaf(__shfl_sync(FULL, h1, i + 1), w2r[i + 1], a1);
                a2 = fmaf(__shfl_sync(FULL, h1, i + 2), w2r[i + 2], a2);
                a3 = fmaf(__shfl_sync(FULL, h1, i + 3), w2r[i + 3], a3);
            }
            float h2 = (a0 + a1) + (a2 + a3);
            h2 = fmaxf(h2, 0.1f * h2);

            acc = fmaxf(acc, h2);
        }

        out[((size_t)qid) * 32 + lane] = acc;
    }
}

extern "C" void kernel_launch(void* const* d_in, const int* in_sizes, int n_in,
                              void* d_out, int out_size) {
    const float* xyz     = (const float*)d_in[0];
    const float* feat    = (const float*)d_in[1];
    const int*   fps_idx = (const int*)  d_in[2];
    const float* W1      = (const float*)d_in[3];
    const float* b1      = (const float*)d_in[4];
    const float* W2      = (const float*)d_in[5];
    const float* b2      = (const float*)d_in[6];
    float* out = (float*)d_out;

    prep_kernel<<<(B_ * NPAIR + 255) / 256, 256>>>(xyz);
    order_kernel<<<NQ / 256, 256>>>(fps_idx);
    // persistent fused kernel: 4 CTAs/SM, work-stealing queue, longest-first
    sa_kernel<<<592, 256>>>(feat, fps_idx, W1, b1, W2, b2, out);
    (void)in_sizes; (void)n_in; (void)out_size;
}

// round 17
// speedup vs baseline: 1.1325x; 1.1325x over previous
#include <cuda_runtime.h>
#include <cuda_fp16.h>

#define B_  4
#define N_  16384
#define M_  4096
#define K_  16
#define R2  0.25f
#define PRE2 0.33f         // prefilter threshold = R2 + margin (>= 3x fp16 err bound)
#define NQ  (B_ * M_)
#define NPAIR (N_ / 2)     // 8192 pair slots per batch
#define LONG_THRESH 4.0f   // |q|^2 above this => long scan: schedule first + prefilter path

// Scratch (device globals; no allocation allowed)
__device__ float4       g_pts[B_ * N_];   // (x, y, z, |p|^2)
__device__ float4       g_n2p[B_ * N_];   // (-2x, -2y, -2z, |p|^2) exact-test array
__device__ uint4        g_hp [B_ * NPAIR];// pair-packed half coords {x2,y2,z2,pad}
__device__ unsigned int g_qctr, g_front, g_back;
__device__ int          g_order[NQ];

// prep: one thread per pair slot (points i = c*64+l and j = i+32).
__global__ __launch_bounds__(256) void prep_kernel(const float* __restrict__ xyz) {
    int t = blockIdx.x * blockDim.x + threadIdx.x;   // 0 .. B_*NPAIR-1
    if (t == 0) { g_qctr = 0; g_front = 0; g_back = 0; }   // graph-replay safe
    if (t >= B_ * NPAIR) return;
    int b  = t >> 13;              // / NPAIR
    int s  = t & (NPAIR - 1);
    int c  = s >> 5;               // 64-point chunk
    int l  = s & 31;
    int gi = b * N_ + c * 64 + l;
    int gj = gi + 32;

    float xi = xyz[3 * gi + 0], yi = xyz[3 * gi + 1], zi = xyz[3 * gi + 2];
    float xj = xyz[3 * gj + 0], yj = xyz[3 * gj + 1], zj = xyz[3 * gj + 2];
    // match jnp.sum(x**2,-1): (x*x + y*y) + z*z, no fma contraction
    float wi = __fadd_rn(__fadd_rn(__fmul_rn(xi, xi), __fmul_rn(yi, yi)), __fmul_rn(zi, zi));
    float wj = __fadd_rn(__fadd_rn(__fmul_rn(xj, xj), __fmul_rn(yj, yj)), __fmul_rn(zj, zj));

    g_pts[gi] = make_float4(xi, yi, zi, wi);
    g_pts[gj] = make_float4(xj, yj, zj, wj);
    // -2*coord is exact (power-of-2 scale + sign flip): exact-test form
    // rn(rn(qw+pw) + dotn) is bit-identical to rn(rn(qw+pw) - rn(2*dot)).
    g_n2p[gi] = make_float4(-2.0f * xi, -2.0f * yi, -2.0f * zi, wi);
    g_n2p[gj] = make_float4(-2.0f * xj, -2.0f * yj, -2.0f * zj, wj);

    __half2 hx = __halves2half2(__float2half_rn(xi), __float2half_rn(xj));
    __half2 hy = __halves2half2(__float2half_rn(yi), __float2half_rn(yj));
    __half2 hz = __halves2half2(__float2half_rn(zi), __float2half_rn(zj));
    uint4 hv;
    hv.x = *(unsigned*)&hx;
    hv.y = *(unsigned*)&hy;
    hv.z = *(unsigned*)&hz;
    hv.w = 0;
    g_hp[t] = hv;
}

// LPT scheduling: long-scan queries (large |q|^2) go to the front of the
// queue, short ones to the back. Processing order doesn't affect results.
__global__ __launch_bounds__(256) void order_kernel(const int* __restrict__ fps_idx) {
    int qid = blockIdx.x * blockDim.x + threadIdx.x;
    if (qid >= NQ) return;
    int b = qid >> 12;
    float w = g_pts[(size_t)b * N_ + fps_idx[qid]].w;
    int pos;
    if (w > LONG_THRESH) pos = (int)atomicAdd(&g_front, 1u);
    else                 pos = NQ - 1 - (int)atomicAdd(&g_back, 1u);
    g_order[pos] = qid;
}

// exact d2 (pre-scaled point): bit-identical to the reference chain.
__device__ __forceinline__ float d2n(float4 q, float4 n) {
    float dotn = __fadd_rn(__fadd_rn(__fmul_rn(q.x, n.x), __fmul_rn(q.y, n.y)),
                           __fmul_rn(q.z, n.z));
    return __fadd_rn(__fadd_rn(q.w, n.w), dotn);
}

// half2 direct-form distance^2 for a point pair (conservative prefilter only)
__device__ __forceinline__ __half2 ddpair(__half2 qx, __half2 qy, __half2 qz, uint4 h) {
    __half2 px = *(__half2*)&h.x;
    __half2 py = *(__half2*)&h.y;
    __half2 pz = *(__half2*)&h.z;
    __half2 dx = __hsub2(qx, px);
    __half2 dy = __hsub2(qy, py);
    __half2 dz = __hsub2(qz, pz);
    __half2 dd = __hmul2(dx, dx);
    dd = __hfma2(dy, dy, dd);
    dd = __hfma2(dz, dz, dd);
    return dd;
}

// shared rank-select over 8 masks: lanes [found, found+T) claim hits in
// ascending group/bit order (== serial walk). Returns updated found.
__device__ __forceinline__ int rank_select(const unsigned* m, int base, int lane,
                                           int found, int& my_idx) {
    int s0 = __popc(m[0]);
    int s1 = s0 + __popc(m[1]);
    int s2 = s1 + __popc(m[2]);
    int s3 = s2 + __popc(m[3]);
    int s4 = s3 + __popc(m[4]);
    int s5 = s4 + __popc(m[5]);
    int s6 = s5 + __popc(m[6]);
    int T  = s6 + __popc(m[7]);
    int r  = lane - found;
    if (r >= 0 && r < T && lane < K_) {
        unsigned mm; int e, off;
        if (r < s3) {
            if (r < s1) {
                if (r < s0) { mm = m[0]; e = 0;  off = 0;  }
                else        { mm = m[1]; e = s0; off = 32; }
            } else {
                if (r < s2) { mm = m[2]; e = s1; off = 64; }
                else        { mm = m[3]; e = s2; off = 96; }
            }
        } else {
            if (r < s5) {
                if (r < s4) { mm = m[4]; e = s3; off = 128; }
                else        { mm = m[5]; e = s4; off = 160; }
            } else {
                if (r < s6) { mm = m[6]; e = s5; off = 192; }
                else        { mm = m[7]; e = s6; off = 224; }
            }
        }
        my_idx = base + off + __fns(mm, 0, (r - e) + 1);
    }
    return found + T;
}

__global__ __launch_bounds__(256, 4) void sa_kernel(
    const float* __restrict__ feat,
    const int*   __restrict__ fps_idx,
    const float* __restrict__ W1,
    const float* __restrict__ b1,
    const float* __restrict__ W2,
    const float* __restrict__ b2,
    float*       __restrict__ out)
{
    const unsigned FULL = 0xffffffffu;
    int lane = threadIdx.x & 31;

    float w1r[6], w2r[32];
    #pragma unroll
    for (int i = 0; i < 6; i++)  w1r[i] = W1[i * 32 + lane];
    #pragma unroll
    for (int i = 0; i < 32; i++) w2r[i] = W2[i * 32 + lane];
    float b1r = b1[lane];
    float b2r = b2[lane];

    // persistent warp: steal one query at a time, longest-first order
    for (;;) {
        int idx;
        if (lane == 0) idx = (int)atomicAdd(&g_qctr, 1u);
        idx = __shfl_sync(FULL, idx, 0);
        if (idx >= NQ) break;
        int qid = g_order[idx];

        int b = qid >> 12;            // / M_ (4096)
        const float4* __restrict__ pts  = g_pts + (size_t)b * N_;
        const float4* __restrict__ n2pb = g_n2p + (size_t)b * N_;

        float4 q = pts[fps_idx[qid]];

        int found  = 0;
        int my_idx = 0;               // lane k (k<K_) owns neighbor k

        if (q.w > LONG_THRESH) {
            // ---- LONG path: fp16 pair prefilter, exact recheck on candidates.
            // Chunks here are almost always empty -> half L1 bytes, fewer instrs.
            const uint4* __restrict__ hp = g_hp + (size_t)b * NPAIR + lane;
            __half2 qx2 = __half2half2(__float2half_rn(q.x));
            __half2 qy2 = __half2half2(__float2half_rn(q.y));
            __half2 qz2 = __half2half2(__float2half_rn(q.z));
            for (int base = 0; base < N_; base += 256, hp += 128) {
                uint4 h0 = hp[0];
                uint4 h1 = hp[32];
                uint4 h2 = hp[64];
                uint4 h3 = hp[96];
                __half2 d0 = ddpair(qx2, qy2, qz2, h0);
                __half2 d1 = ddpair(qx2, qy2, qz2, h1);
                __half2 d2 = ddpair(qx2, qy2, qz2, h2);
                __half2 d3 = ddpair(qx2, qy2, qz2, h3);
                unsigned c0 = __ballot_sync(FULL, __low2float(d0)  <= PRE2);
                unsigned c1 = __ballot_sync(FULL, __high2float(d0) <= PRE2);
                unsigned c2 = __ballot_sync(FULL, __low2float(d1)  <= PRE2);
                unsigned c3 = __ballot_sync(FULL, __high2float(d1) <= PRE2);
                unsigned c4 = __ballot_sync(FULL, __low2float(d2)  <= PRE2);
                unsigned c5 = __ballot_sync(FULL, __high2float(d2) <= PRE2);
                unsigned c6 = __ballot_sync(FULL, __low2float(d3)  <= PRE2);
                unsigned c7 = __ballot_sync(FULL, __high2float(d3) <= PRE2);
                unsigned any = (c0 | c1) | (c2 | c3) | ((c4 | c5) | (c6 | c7));
                if (any) {
                    // exact recheck: candidates only, reference-exact arithmetic
                    unsigned cm[8] = {c0, c1, c2, c3, c4, c5, c6, c7};
                    unsigned m[8];
                    #pragma unroll
                    for (int j = 0; j < 8; j++) {
                        bool e = false;
                        if ((cm[j] >> lane) & 1u) {
                            e = d2n(q, n2pb[base + j * 32 + lane]) <= R2;
                        }
                        m[j] = __ballot_sync(FULL, e);
                    }
                    found = rank_select(m, base, lane, found, my_idx);
                    if (found >= K_) { found = K_; break; }
                }
            }
        } else {
            // ---- SHORT path: exact scan (hit-dense chunks; no prefilter tax).
            const float4* __restrict__ pl = n2pb + lane;
            for (int base = 0; base < N_; base += 256, pl += 256) {
                float4 p0 = pl[0];
                float4 p1 = pl[32];
                float4 p2 = pl[64];
                float4 p3 = pl[96];
                float4 p4 = pl[128];
                float4 p5 = pl[160];
                float4 p6 = pl[192];
                float4 p7 = pl[224];
                unsigned m[8];
                m[0] = __ballot_sync(FULL, d2n(q, p0) <= R2);
                m[1] = __ballot_sync(FULL, d2n(q, p1) <= R2);
                m[2] = __ballot_sync(FULL, d2n(q, p2) <= R2);
                m[3] = __ballot_sync(FULL, d2n(q, p3) <= R2);
                m[4] = __ballot_sync(FULL, d2n(q, p4) <= R2);
                m[5] = __ballot_sync(FULL, d2n(q, p5) <= R2);
                m[6] = __ballot_sync(FULL, d2n(q, p6) <= R2);
                m[7] = __ballot_sync(FULL, d2n(q, p7) <= R2);
                unsigned any = (m[0] | m[1]) | (m[2] | m[3]) | ((m[4] | m[5]) | (m[6] | m[7]));
                if (any) {
                    found = rank_select(m, base, lane, found, my_idx);
                    if (found >= K_) { found = K_; break; }
                }
            }
        }

        // pad missing neighbors with the first valid one (reference
        // semantics); found >= 1 always (query is in its own ball).
        int idx0 = __shfl_sync(FULL, my_idx, 0);
        if (lane >= found) my_idx = idx0;
        int kmax = found;                     // padded dups can't change max

        // ---- MLP + maxpool: lane j owns output channel j ----
        const float* __restrict__ featb = feat + (size_t)b * N_ * 3;
        float acc = -3.402823466e38f;

        #pragma unroll 1
        for (int k = 0; k < kmax; k++) {
            int g = __shfl_sync(FULL, my_idx, k);
            float4 p = pts[g];                    // broadcast load (L1/L2 hit)
            float f0 = featb[3 * g + 0];
            float f1 = featb[3 * g + 1];
            float f2 = featb[3 * g + 2];
            float i0 = p.x - q.x, i1 = p.y - q.y, i2 = p.z - q.z;

            float h1 = b1r;
            h1 += i0 * w1r[0];
            h1 += i1 * w1r[1];
            h1 += i2 * w1r[2];
            h1 += f0 * w1r[3];
            h1 += f1 * w1r[4];
            h1 += f2 * w1r[5];
            h1 = fmaxf(h1, 0.1f * h1);            // leaky relu

            // 4 accumulator chains to break the serial FMA dependency
            float a0 = b2r, a1 = 0.f, a2 = 0.f, a3 = 0.f;
            #pragma unroll
            for (int i = 0; i < 32; i += 4) {
                a0 = fmaf(__shfl_sync(FULL, h1, i + 0), w2r[i + 0], a0);
                a1 = fmaf(__shfl_sync(FULL, h1, i + 1), w2r[i + 1], a1);
                a2 = fmaf(__shfl_sync(FULL, h1, i + 2), w2r[i + 2], a2);
                a3 = fmaf(__shfl_sync(FULL, h1, i + 3), w2r[i + 3], a3);
            }
            float h2 = (a0 + a1) + (a2 + a3);
            h2 = fmaxf(h2, 0.1f * h2);

            acc = fmaxf(acc, h2);
        }

        out[((size_t)qid) * 32 + lane] = acc;
    }
}

extern "C" void kernel_launch(void* const* d_in, const int* in_sizes, int n_in,
                              void* d_out, int out_size) {
    const float* xyz     = (const float*)d_in[0];
    const float* feat    = (const float*)d_in[1];
    const int*   fps_idx = (const int*)  d_in[2];
    const float* W1      = (const float*)d_in[3];
    const float* b1      = (const float*)d_in[4];
    const float* W2      = (const float*)d_in[5];
    const float* b2      = (const float*)d_in[6];
    float* out = (float*)d_out;

    prep_kernel<<<(B_ * NPAIR + 255) / 256, 256>>>(xyz);
    order_kernel<<<NQ / 256, 256>>>(fps_idx);
    // persistent fused kernel: 4 CTAs/SM, work-stealing queue, longest-first
    sa_kernel<<<592, 256>>>(feat, fps_idx, W1, b1, W2, b2, out);
    (void)in_sizes; (void)n_in; (void)out_size;
}